// round 4
// baseline (speedup 1.0000x reference)
#include <cuda_runtime.h>
#include <cstdint>

#define NS 8          // tokens per node
#define DD 128        // model dim
#define NH 4          // heads
#define DH 32         // head dim

#define MAXN 20000
#define MAXM (MAXN * NS)          // 160000 rows
#define MAXE 100000

// -------- device scratch (allocation-free rule: __device__ globals) --------
__device__ float g_dstproj[MAXM * 384];   // [q|k|v] per dst-node token
__device__ float g_srcproj[MAXM * 256];   // [k|v] per src-node token (Wb folded)
__device__ float g_sum[MAXM * DD];        // pre-Wo segment sum
__device__ float g_cnt[MAXN];
__device__ float g_Wf[256 * DD];          // folded [Wk@Wb ; Wv@Wb]
__device__ float g_bf[256];               // folded biases
__device__ int   g_hist[MAXN];
__device__ int   g_off[MAXN + 1];
__device__ int   g_cur[MAXN];
__device__ int   g_csr[MAXE];             // src node per edge, grouped by dst

// ---------------------------------------------------------------------------
__global__ void zero2_int_kernel(int* __restrict__ a, int* __restrict__ b, int n) {
    int i = blockIdx.x * blockDim.x + threadIdx.x;
    if (i < n) { a[i] = 0; b[i] = 0; }
}

__global__ void hist_kernel(const int* __restrict__ ei, int E, int* __restrict__ hist) {
    int i = blockIdx.x * blockDim.x + threadIdx.x;
    if (i < E) atomicAdd(hist + ei[E + i], 1);
}

__global__ __launch_bounds__(1024)
void scan_kernel(const int* __restrict__ hist, int* __restrict__ off, int N) {
    __shared__ int part[1025];
    const int t = threadIdx.x;
    const int chunk = (N + 1023) >> 10;
    const int lo = t * chunk;
    const int hi = min(lo + chunk, N);
    int s = 0;
    for (int i = lo; i < hi; i++) s += hist[i];
    part[t] = s;
    __syncthreads();
    if (t == 0) {
        int acc = 0;
        for (int i = 0; i < 1024; i++) { int v = part[i]; part[i] = acc; acc += v; }
        part[1024] = acc;
        off[N] = acc;
    }
    __syncthreads();
    int acc = part[t];
    for (int i = lo; i < hi; i++) { off[i] = acc; acc += hist[i]; }
}

__global__ void scatter_kernel(const int* __restrict__ ei, int E,
                               const int* __restrict__ off, int* __restrict__ cur,
                               int* __restrict__ csr) {
    int i = blockIdx.x * blockDim.x + threadIdx.x;
    if (i < E) {
        int dst = ei[E + i];
        int pos = atomicAdd(cur + dst, 1);
        csr[off[dst] + pos] = ei[i];
    }
}

__global__ void cnt_kernel(const int* __restrict__ off, float* __restrict__ cnt, int N) {
    int i = blockIdx.x * blockDim.x + threadIdx.x;
    if (i < N) cnt[i] = (float)(off[i + 1] - off[i]);
}

// Fold Wb into K/V projections: Wf[o,d] = sum_j Win[128+o, j] * Wb[j, d]
__global__ void fold_kernel(const float* __restrict__ Win, const float* __restrict__ Wb,
                            const float* __restrict__ bb, const float* __restrict__ bin,
                            float* __restrict__ Wf, float* __restrict__ bf) {
    int id = blockIdx.x * blockDim.x + threadIdx.x;
    int o = id >> 7, d = id & 127;
    const float* wrow = Win + (size_t)(128 + o) * DD;
    float acc = 0.f;
    #pragma unroll 8
    for (int j = 0; j < DD; j++) acc += wrow[j] * Wb[j * DD + d];
    Wf[o * DD + d] = acc;
    if (d == 0) {
        float b = 0.f;
        for (int j = 0; j < DD; j++) b += wrow[j] * bb[j];
        bf[o] = b + bin[128 + o];
    }
}

// ---------------------------------------------------------------------------
__device__ __forceinline__ uint32_t f2tf32(float x) {
    uint32_t r;
    asm("cvt.rna.tf32.f32 %0, %1;" : "=r"(r) : "f"(x));
    return r;
}

// C[M, Nout] = alpha * ( rowscale(A) @ B^T + bpresent*bias ), optionally +=.
// Block tile 128x128, 8 warps in 2x4, warp tile 64x32 (4x4 m16n8k8 tiles).
__global__ __launch_bounds__(256)
void gemm_tf32(const float* __restrict__ A, const float* __restrict__ B,
               const float* __restrict__ bias, float* __restrict__ C,
               int ldc, const float* __restrict__ cnt,
               float alpha, int accumulate) {
    __shared__ uint32_t As[128][36];
    __shared__ uint32_t Bs[128][36];

    const int t    = threadIdx.x;
    const int lane = t & 31;
    const int warp = t >> 5;
    const int wm   = warp >> 2;          // 0..1  -> 64-row slice
    const int wn   = warp & 3;           // 0..3  -> 32-col slice
    const int m0   = blockIdx.y * 128;
    const int n0   = blockIdx.x * 128;
    const int lg   = lane >> 2;
    const int lt   = lane & 3;

    float acc[4][4][4] = {};             // [mtile][ntile][c]

    for (int k0 = 0; k0 < 128; k0 += 32) {
        #pragma unroll
        for (int r = 0; r < 4; r++) {
            int idx = t + r * 256;
            int row = idx >> 3, c4 = idx & 7;
            float4 v = *(const float4*)(A + (size_t)(m0 + row) * DD + k0 + c4 * 4);
            if (cnt) {
                float c = cnt[(m0 + row) >> 3];
                float rs = (c > 0.f) ? (1.f / c) : 0.f;
                v.x *= rs; v.y *= rs; v.z *= rs; v.w *= rs;
            }
            As[row][c4 * 4 + 0] = f2tf32(v.x);
            As[row][c4 * 4 + 1] = f2tf32(v.y);
            As[row][c4 * 4 + 2] = f2tf32(v.z);
            As[row][c4 * 4 + 3] = f2tf32(v.w);
        }
        #pragma unroll
        for (int r = 0; r < 4; r++) {
            int idx = t + r * 256;
            int row = idx >> 3, c4 = idx & 7;
            float4 v = *(const float4*)(B + (size_t)(n0 + row) * DD + k0 + c4 * 4);
            Bs[row][c4 * 4 + 0] = f2tf32(v.x);
            Bs[row][c4 * 4 + 1] = f2tf32(v.y);
            Bs[row][c4 * 4 + 2] = f2tf32(v.z);
            Bs[row][c4 * 4 + 3] = f2tf32(v.w);
        }
        __syncthreads();

        #pragma unroll
        for (int ks = 0; ks < 4; ks++) {
            const int kk = ks * 8;
            uint32_t af[4][4], bfr[4][2];
            #pragma unroll
            for (int mt = 0; mt < 4; mt++) {
                int rbase = wm * 64 + mt * 16;
                af[mt][0] = As[rbase + lg][kk + lt];
                af[mt][1] = As[rbase + 8 + lg][kk + lt];
                af[mt][2] = As[rbase + lg][kk + 4 + lt];
                af[mt][3] = As[rbase + 8 + lg][kk + 4 + lt];
            }
            #pragma unroll
            for (int nt = 0; nt < 4; nt++) {
                int nrow = wn * 32 + nt * 8 + lg;
                bfr[nt][0] = Bs[nrow][kk + lt];
                bfr[nt][1] = Bs[nrow][kk + 4 + lt];
            }
            #pragma unroll
            for (int mt = 0; mt < 4; mt++) {
                #pragma unroll
                for (int nt = 0; nt < 4; nt++) {
                    asm volatile(
                        "mma.sync.aligned.m16n8k8.row.col.f32.tf32.tf32.f32 "
                        "{%0,%1,%2,%3}, {%4,%5,%6,%7}, {%8,%9}, {%0,%1,%2,%3};"
                        : "+f"(acc[mt][nt][0]), "+f"(acc[mt][nt][1]),
                          "+f"(acc[mt][nt][2]), "+f"(acc[mt][nt][3])
                        : "r"(af[mt][0]), "r"(af[mt][1]), "r"(af[mt][2]), "r"(af[mt][3]),
                          "r"(bfr[nt][0]), "r"(bfr[nt][1]));
                }
            }
        }
        __syncthreads();
    }

    #pragma unroll
    for (int mt = 0; mt < 4; mt++) {
        int r0 = m0 + wm * 64 + mt * 16 + lg;
        int r1 = r0 + 8;
        float bp0 = 1.f, bp1 = 1.f;
        if (cnt) {
            bp0 = (cnt[r0 >> 3] > 0.f) ? 1.f : 0.f;
            bp1 = (cnt[r1 >> 3] > 0.f) ? 1.f : 0.f;
        }
        #pragma unroll
        for (int nt = 0; nt < 4; nt++) {
            int col = n0 + wn * 32 + nt * 8 + 2 * lt;
            float b0 = bias[col], b1 = bias[col + 1];
            float v00 = alpha * (acc[mt][nt][0] + bp0 * b0);
            float v01 = alpha * (acc[mt][nt][1] + bp0 * b1);
            float v10 = alpha * (acc[mt][nt][2] + bp1 * b0);
            float v11 = alpha * (acc[mt][nt][3] + bp1 * b1);
            float* p0 = C + (size_t)r0 * ldc + col;
            float* p1 = C + (size_t)r1 * ldc + col;
            if (accumulate) {
                p0[0] += v00; p0[1] += v01;
                p1[0] += v10; p1[1] += v11;
            } else {
                *(float2*)p0 = make_float2(v00, v01);
                *(float2*)p1 = make_float2(v10, v11);
            }
        }
    }
}

// ---------------------------------------------------------------------------
__device__ __forceinline__ void cp_async16(void* smem, const void* gmem) {
    uint32_t s = (uint32_t)__cvta_generic_to_shared(smem);
    asm volatile("cp.async.cg.shared.global [%0], [%1], 16;" :: "r"(s), "l"(gmem));
}
__device__ __forceinline__ void cp_commit() {
    asm volatile("cp.async.commit_group;");
}
template <int N> __device__ __forceinline__ void cp_wait() {
    asm volatile("cp.async.wait_group %0;" :: "n"(N));
}

// One block (4 warps) per dst node; WARP-PER-EDGE. Each lane owns one
// (head, query) pair: softmax is fully lane-local. Each warp streams its
// stride-4 subset of edges through a private double-buffered smem stage.
// No block barriers in the edge loop; deterministic fixed-order reduce.
//
// Dynamic smem layout (floats):
//   svd   [8 rows][4 heads * 36]          : 1152
//   accum [32 pairs][33]                  : 1056
//   elist (ints)                          : 128
//   bufs: 4 warps x 2 bufs x (k 1152 + v 1152) : 18432
#define SORT_CAP 128
#define HPAD 36
#define ROWF (4 * HPAD)   // 144 floats per token row (per-head padded)
__global__ __launch_bounds__(128)
void node_attn_kernel(const int* __restrict__ off, const int* __restrict__ csr,
                      const float* __restrict__ dstproj,
                      const float* __restrict__ srcproj,
                      float* __restrict__ gsum) {
    extern __shared__ float sm[];
    float* svd   = sm;                  // 1152
    float* accum = sm + 1152;           // 1056
    int*   elist = (int*)(sm + 2208);   // 128 ints
    float* bufs  = sm + 2336;           // 8 * 2304

    const int n    = blockIdx.x;
    const int t    = threadIdx.x;
    const int w    = t >> 5;
    const int lane = t & 31;
    const int h    = lane >> 3;
    const int qi   = lane & 7;
    const int off0 = off[n];
    const int deg  = off[n + 1] - off0;
    if (deg == 0) return;

    const bool cached = (deg <= SORT_CAP);
    if (cached) {
        for (int i = t; i < deg; i += 128) elist[i] = csr[off0 + i];
    }
    // load dst V into per-head padded smem: 256 float4
    const float* dp = dstproj + (size_t)n * (NS * 384);
    for (int i = t; i < 256; i += 128) {
        int kk = i >> 5, c = i & 31, hh = c >> 3, uu = c & 7;
        *(float4*)(svd + kk * ROWF + hh * HPAD + uu * 4) =
            *(const float4*)(dp + kk * 384 + 256 + c * 4);
    }
    __syncthreads();
    if (cached && t == 0) {   // sort for deterministic accumulation order
        for (int i = 1; i < deg; i++) {
            int v = elist[i], j = i - 1;
            while (j >= 0 && elist[j] > v) { elist[j + 1] = elist[j]; j--; }
            elist[j + 1] = v;
        }
    }
    __syncthreads();

    const float scale = 0.17677669529663687f;   // 1/sqrt(32)

    // per-lane q slice + dst-key logits (from global; L1-resident)
    float4 qr[8];
    #pragma unroll
    for (int u = 0; u < 8; u++)
        qr[u] = *(const float4*)(dp + qi * 384 + h * DH + u * 4);
    float ldl[8];
    #pragma unroll
    for (int kk = 0; kk < 8; kk++) {
        const float* kp = dp + kk * 384 + 128 + h * DH;
        float a = 0.f;
        #pragma unroll
        for (int u = 0; u < 8; u++) {
            float4 kr = *(const float4*)(kp + u * 4);
            a += qr[u].x * kr.x + qr[u].y * kr.y + qr[u].z * kr.z + qr[u].w * kr.w;
        }
        ldl[kk] = a * scale;
    }

    float o[32];
    #pragma unroll
    for (int d = 0; d < 32; d++) o[d] = 0.f;

    const int nmy = (deg > w) ? ((deg - w + 3) >> 2) : 0;
    float* buf0 = bufs + (w * 2 + 0) * 2304;
    float* buf1 = bufs + (w * 2 + 1) * 2304;
    const int lh = lane >> 3, lu = lane & 7;

    // prologue: stage first edge
    if (nmy > 0) {
        int sn = cached ? elist[w] : csr[off0 + w];
        const float* sp = srcproj + (size_t)sn * (NS * 256);
        #pragma unroll
        for (int r = 0; r < 8; r++) {
            cp_async16(buf0 + r * ROWF + lh * HPAD + lu * 4, sp + r * 256 + lane * 4);
            cp_async16(buf0 + 1152 + r * ROWF + lh * HPAD + lu * 4, sp + r * 256 + 128 + lane * 4);
        }
        cp_commit();
    }

    for (int i = 0; i < nmy; i++) {
        float* kbb = (i & 1) ? buf1 : buf0;
        if (i + 1 < nmy) {
            float* nb = (i & 1) ? buf0 : buf1;
            int sn = cached ? elist[w + 4 * (i + 1)] : csr[off0 + w + 4 * (i + 1)];
            const float* sp = srcproj + (size_t)sn * (NS * 256);
            #pragma unroll
            for (int r = 0; r < 8; r++) {
                cp_async16(nb + r * ROWF + lh * HPAD + lu * 4, sp + r * 256 + lane * 4);
                cp_async16(nb + 1152 + r * ROWF + lh * HPAD + lu * 4, sp + r * 256 + 128 + lane * 4);
            }
            cp_commit();
            cp_wait<1>();
        } else {
            cp_wait<0>();
        }
        __syncwarp();

        const float* vbb = kbb + 1152;
        // logits: 8 dst (precomputed) + 8 src
        float l[16];
        #pragma unroll
        for (int kk = 0; kk < 8; kk++) l[kk] = ldl[kk];
        #pragma unroll
        for (int kk = 0; kk < 8; kk++) {
            const float* kp = kbb + kk * ROWF + h * HPAD;
            float a = 0.f;
            #pragma unroll
            for (int u = 0; u < 8; u++) {
                float4 kr = *(const float4*)(kp + u * 4);
                a += qr[u].x * kr.x + qr[u].y * kr.y + qr[u].z * kr.z + qr[u].w * kr.w;
            }
            l[8 + kk] = a * scale;
        }
        // lane-local softmax over 16 keys
        float m = l[0];
        #pragma unroll
        for (int k2 = 1; k2 < 16; k2++) m = fmaxf(m, l[k2]);
        float p[16], es = 0.f;
        #pragma unroll
        for (int k2 = 0; k2 < 16; k2++) { p[k2] = __expf(l[k2] - m); es += p[k2]; }
        float inv = 1.f / es;
        // o += att @ [v_dst ; v_src]
        #pragma unroll
        for (int kk = 0; kk < 8; kk++) {
            float ad = p[kk] * inv, as = p[8 + kk] * inv;
            const float* vd = svd + kk * ROWF + h * HPAD;
            const float* vs = vbb + kk * ROWF + h * HPAD;
            #pragma unroll
            for (int u = 0; u < 8; u++) {
                float4 v1 = *(const float4*)(vd + u * 4);
                float4 v2 = *(const float4*)(vs + u * 4);
                o[u * 4 + 0] += ad * v1.x + as * v2.x;
                o[u * 4 + 1] += ad * v1.y + as * v2.y;
                o[u * 4 + 2] += ad * v1.z + as * v2.z;
                o[u * 4 + 3] += ad * v1.w + as * v2.w;
            }
        }
        __syncwarp();
    }

    // fixed-order cross-warp reduce (deterministic)
    for (int ww = 0; ww < 4; ww++) {
        if (w == ww) {
            float* ap = accum + lane * 33;
            if (ww == 0) {
                #pragma unroll
                for (int d = 0; d < 32; d++) ap[d] = o[d];
            } else {
                #pragma unroll
                for (int d = 0; d < 32; d++) ap[d] += o[d];
            }
        }
        __syncthreads();
    }
    // write out: gsum[n][qi*128 + h*32 + c]
    float* outp = gsum + (size_t)n * (NS * DD);
    for (int i = t; i < 256; i += 128) {
        int pr = i >> 3, u = i & 7;
        int hh = pr >> 3, qq = pr & 7;
        const float* ap = accum + pr * 33 + u * 4;
        *(float4*)(outp + qq * DD + hh * DH + u * 4) =
            make_float4(ap[0], ap[1], ap[2], ap[3]);
    }
}

// ---------------------------------------------------------------------------
extern "C" void kernel_launch(void* const* d_in, const int* in_sizes, int n_in,
                              void* d_out, int out_size) {
    const float* x_a = (const float*)d_in[0];
    const float* x_b = (const float*)d_in[1];
    const int* ei[3] = {(const int*)d_in[2], (const int*)d_in[3], (const int*)d_in[4]};
    const int E  = in_sizes[2] / 2;
    const int Nn = in_sizes[0] / (NS * DD);
    const int M  = Nn * NS;

    float *dstproj, *srcproj, *sum, *cnt, *Wf, *bf;
    int *hist, *off, *cur, *csr;
    cudaGetSymbolAddress((void**)&dstproj, g_dstproj);
    cudaGetSymbolAddress((void**)&srcproj, g_srcproj);
    cudaGetSymbolAddress((void**)&sum, g_sum);
    cudaGetSymbolAddress((void**)&cnt, g_cnt);
    cudaGetSymbolAddress((void**)&Wf, g_Wf);
    cudaGetSymbolAddress((void**)&bf, g_bf);
    cudaGetSymbolAddress((void**)&hist, g_hist);
    cudaGetSymbolAddress((void**)&off, g_off);
    cudaGetSymbolAddress((void**)&cur, g_cur);
    cudaGetSymbolAddress((void**)&csr, g_csr);

    const int ATTN_SMEM = (2336 + 8 * 2304) * 4;   // 83072 B
    cudaFuncSetAttribute(node_attn_kernel,
                         cudaFuncAttributeMaxDynamicSharedMemorySize, ATTN_SMEM);

    float* out = (float*)d_out;

    const float* xsrc[3] = {x_a, x_b, x_a};
    const float* xdst[3] = {x_b, x_a, x_a};
    float* outp[3]  = {out + (size_t)M * DD, out, out};
    float alpha[3]  = {1.f, 0.5f, 0.5f};
    int   accum[3]  = {0, 0, 1};

    for (int r = 0; r < 3; r++) {
        const float* Wb  = (const float*)d_in[5 + r * 6 + 0];
        const float* bb  = (const float*)d_in[5 + r * 6 + 1];
        const float* Win = (const float*)d_in[5 + r * 6 + 2];
        const float* bin = (const float*)d_in[5 + r * 6 + 3];
        const float* Wo  = (const float*)d_in[5 + r * 6 + 4];
        const float* bo  = (const float*)d_in[5 + r * 6 + 5];

        // ---- CSR build (by dst) ----
        zero2_int_kernel<<<(Nn + 255) / 256, 256>>>(hist, cur, Nn);
        hist_kernel<<<(E + 255) / 256, 256>>>(ei[r], E, hist);
        scan_kernel<<<1, 1024>>>(hist, off, Nn);
        scatter_kernel<<<(E + 255) / 256, 256>>>(ei[r], E, off, cur, csr);
        cnt_kernel<<<(Nn + 255) / 256, 256>>>(off, cnt, Nn);

        fold_kernel<<<128, 256>>>(Win, Wb, bb, bin, Wf, bf);

        // per-node projections (dst: q|k|v ; src: folded k|v)
        gemm_tf32<<<dim3(3, M / 128), 256>>>(xdst[r], Win, bin, dstproj, 384, nullptr, 1.f, 0);
        gemm_tf32<<<dim3(2, M / 128), 256>>>(xsrc[r], Wf, bf, srcproj, 256, nullptr, 1.f, 0);

        // grouped per-node attention, warp-per-edge, no atomics
        node_attn_kernel<<<Nn, 128, ATTN_SMEM>>>(off, csr, dstproj, srcproj, sum);

        // mean + Wo + bias (+combine across relations)
        gemm_tf32<<<dim3(1, M / 128), 256>>>(sum, Wo, bo, outp[r], DD, cnt, alpha[r], accum[r]);
    }
}

// round 5
// speedup vs baseline: 1.2918x; 1.2918x over previous
#include <cuda_runtime.h>
#include <cstdint>

#define NS 8          // tokens per node
#define DD 128        // model dim
#define NH 4          // heads
#define DH 32         // head dim

#define MAXN 20000
#define MAXM (MAXN * NS)          // 160000 rows
#define MAXE 100000

// -------- device scratch (allocation-free rule: __device__ globals) --------
__device__ float g_dstproj[MAXM * 384];   // [q|k|v] per dst-node token
__device__ float g_srcproj[MAXM * 256];   // [k|v] per src-node token (Wb folded)
__device__ float g_sum[MAXM * DD];        // pre-Wo segment sum
__device__ float g_cnt[MAXN];
__device__ float g_Wf[256 * DD];          // folded [Wk@Wb ; Wv@Wb]
__device__ float g_bf[256];               // folded biases
__device__ int   g_hist[MAXN];
__device__ int   g_off[MAXN + 1];
__device__ int   g_cur[MAXN];
__device__ int   g_csr[MAXE];             // src node per edge, grouped by dst

// ---------------------------------------------------------------------------
__global__ void zero2_int_kernel(int* __restrict__ a, int* __restrict__ b, int n) {
    int i = blockIdx.x * blockDim.x + threadIdx.x;
    if (i < n) { a[i] = 0; b[i] = 0; }
}

__global__ void hist_kernel(const int* __restrict__ ei, int E, int* __restrict__ hist) {
    int i = blockIdx.x * blockDim.x + threadIdx.x;
    if (i < E) atomicAdd(hist + ei[E + i], 1);
}

__global__ __launch_bounds__(1024)
void scan_kernel(const int* __restrict__ hist, int* __restrict__ off, int N) {
    __shared__ int part[1025];
    const int t = threadIdx.x;
    const int chunk = (N + 1023) >> 10;
    const int lo = t * chunk;
    const int hi = min(lo + chunk, N);
    int s = 0;
    for (int i = lo; i < hi; i++) s += hist[i];
    part[t] = s;
    __syncthreads();
    if (t == 0) {
        int acc = 0;
        for (int i = 0; i < 1024; i++) { int v = part[i]; part[i] = acc; acc += v; }
        part[1024] = acc;
        off[N] = acc;
    }
    __syncthreads();
    int acc = part[t];
    for (int i = lo; i < hi; i++) { off[i] = acc; acc += hist[i]; }
}

__global__ void scatter_kernel(const int* __restrict__ ei, int E,
                               const int* __restrict__ off, int* __restrict__ cur,
                               int* __restrict__ csr) {
    int i = blockIdx.x * blockDim.x + threadIdx.x;
    if (i < E) {
        int dst = ei[E + i];
        int pos = atomicAdd(cur + dst, 1);
        csr[off[dst] + pos] = ei[i];
    }
}

__global__ void cnt_kernel(const int* __restrict__ off, float* __restrict__ cnt, int N) {
    int i = blockIdx.x * blockDim.x + threadIdx.x;
    if (i < N) cnt[i] = (float)(off[i + 1] - off[i]);
}

// Fold Wb into K/V projections: Wf[o,d] = sum_j Win[128+o, j] * Wb[j, d]
__global__ void fold_kernel(const float* __restrict__ Win, const float* __restrict__ Wb,
                            const float* __restrict__ bb, const float* __restrict__ bin,
                            float* __restrict__ Wf, float* __restrict__ bf) {
    int id = blockIdx.x * blockDim.x + threadIdx.x;
    int o = id >> 7, d = id & 127;
    const float* wrow = Win + (size_t)(128 + o) * DD;
    float acc = 0.f;
    #pragma unroll 8
    for (int j = 0; j < DD; j++) acc += wrow[j] * Wb[j * DD + d];
    Wf[o * DD + d] = acc;
    if (d == 0) {
        float b = 0.f;
        for (int j = 0; j < DD; j++) b += wrow[j] * bb[j];
        bf[o] = b + bin[128 + o];
    }
}

// ---------------------------------------------------------------------------
__device__ __forceinline__ uint32_t f2tf32(float x) {
    uint32_t r;
    asm("cvt.rna.tf32.f32 %0, %1;" : "=r"(r) : "f"(x));
    return r;
}
__device__ __forceinline__ void cp_async16(void* smem, const void* gmem) {
    uint32_t s = (uint32_t)__cvta_generic_to_shared(smem);
    asm volatile("cp.async.cg.shared.global [%0], [%1], 16;" :: "r"(s), "l"(gmem));
}
__device__ __forceinline__ void cp_commit() {
    asm volatile("cp.async.commit_group;");
}
template <int N> __device__ __forceinline__ void cp_wait() {
    asm volatile("cp.async.wait_group %0;" :: "n"(N));
}

// C[M, Nout] = alpha * ( rowscale * (A @ B^T) + bpresent*bias ), optionally +=.
// A: [M,128] row-major, B: [Nout,128] row-major. 128x64 block tile, 8 warps
// each 32x32 (2x4 m16n8k8 tf32 tiles). fp32 staged via cp.async double
// buffer; tf32 conversion at fragment load; rowscale applied in epilogue.
#define GEMM_SMEM ((2 * 128 * 36 + 2 * 64 * 36) * 4)   // 55296 B
__global__ __launch_bounds__(256)
void gemm_tf32(const float* __restrict__ A, const float* __restrict__ B,
               const float* __restrict__ bias, float* __restrict__ C,
               int ldc, const float* __restrict__ cnt,
               float alpha, int accumulate) {
    extern __shared__ float sm[];
    float* As = sm;                 // [2][128][36]
    float* Bs = sm + 2 * 128 * 36;  // [2][64][36]

    const int t    = threadIdx.x;
    const int lane = t & 31;
    const int warp = t >> 5;
    const int wm   = warp >> 1;          // 0..3 -> 32-row slice
    const int wn   = warp & 1;           // 0..1 -> 32-col slice
    const int m0   = blockIdx.y * 128;
    const int n0   = blockIdx.x * 64;
    const int lg   = lane >> 2;
    const int lt   = lane & 3;

    float acc[2][4][4] = {};

    auto load_stage = [&](int ks) {
        const int k0 = ks * 32;
        float* Ab = As + (ks & 1) * (128 * 36);
        float* Bb = Bs + (ks & 1) * (64 * 36);
        #pragma unroll
        for (int r = 0; r < 4; r++) {
            int idx = t + r * 256;
            int row = idx >> 3, c4 = idx & 7;
            cp_async16(Ab + row * 36 + c4 * 4,
                       A + (size_t)(m0 + row) * DD + k0 + c4 * 4);
        }
        #pragma unroll
        for (int r = 0; r < 2; r++) {
            int idx = t + r * 256;
            int row = idx >> 3, c4 = idx & 7;
            cp_async16(Bb + row * 36 + c4 * 4,
                       B + (size_t)(n0 + row) * DD + k0 + c4 * 4);
        }
        cp_commit();
    };

    load_stage(0);

    #pragma unroll
    for (int kc = 0; kc < 4; kc++) {
        if (kc < 3) { load_stage(kc + 1); cp_wait<1>(); }
        else        { cp_wait<0>(); }
        __syncthreads();

        const float* Ab = As + (kc & 1) * (128 * 36);
        const float* Bb = Bs + (kc & 1) * (64 * 36);
        #pragma unroll
        for (int ks = 0; ks < 4; ks++) {
            const int kk = ks * 8;
            uint32_t af[2][4], bfr[4][2];
            #pragma unroll
            for (int mt = 0; mt < 2; mt++) {
                int rbase = wm * 32 + mt * 16;
                af[mt][0] = f2tf32(Ab[(rbase + lg) * 36 + kk + lt]);
                af[mt][1] = f2tf32(Ab[(rbase + 8 + lg) * 36 + kk + lt]);
                af[mt][2] = f2tf32(Ab[(rbase + lg) * 36 + kk + 4 + lt]);
                af[mt][3] = f2tf32(Ab[(rbase + 8 + lg) * 36 + kk + 4 + lt]);
            }
            #pragma unroll
            for (int nt = 0; nt < 4; nt++) {
                int nrow = wn * 32 + nt * 8 + lg;
                bfr[nt][0] = f2tf32(Bb[nrow * 36 + kk + lt]);
                bfr[nt][1] = f2tf32(Bb[nrow * 36 + kk + 4 + lt]);
            }
            #pragma unroll
            for (int mt = 0; mt < 2; mt++) {
                #pragma unroll
                for (int nt = 0; nt < 4; nt++) {
                    asm volatile(
                        "mma.sync.aligned.m16n8k8.row.col.f32.tf32.tf32.f32 "
                        "{%0,%1,%2,%3}, {%4,%5,%6,%7}, {%8,%9}, {%0,%1,%2,%3};"
                        : "+f"(acc[mt][nt][0]), "+f"(acc[mt][nt][1]),
                          "+f"(acc[mt][nt][2]), "+f"(acc[mt][nt][3])
                        : "r"(af[mt][0]), "r"(af[mt][1]), "r"(af[mt][2]), "r"(af[mt][3]),
                          "r"(bfr[nt][0]), "r"(bfr[nt][1]));
                }
            }
        }
        __syncthreads();
    }

    #pragma unroll
    for (int mt = 0; mt < 2; mt++) {
        int r0 = m0 + wm * 32 + mt * 16 + lg;
        int r1 = r0 + 8;
        float bp0 = 1.f, bp1 = 1.f, rs0 = 1.f, rs1 = 1.f;
        if (cnt) {
            float c0 = cnt[r0 >> 3], c1 = cnt[r1 >> 3];
            bp0 = (c0 > 0.f) ? 1.f : 0.f;  rs0 = (c0 > 0.f) ? (1.f / c0) : 0.f;
            bp1 = (c1 > 0.f) ? 1.f : 0.f;  rs1 = (c1 > 0.f) ? (1.f / c1) : 0.f;
        }
        #pragma unroll
        for (int nt = 0; nt < 4; nt++) {
            int col = n0 + wn * 32 + nt * 8 + 2 * lt;
            float b0 = bias[col], b1 = bias[col + 1];
            float v00 = alpha * (rs0 * acc[mt][nt][0] + bp0 * b0);
            float v01 = alpha * (rs0 * acc[mt][nt][1] + bp0 * b1);
            float v10 = alpha * (rs1 * acc[mt][nt][2] + bp1 * b0);
            float v11 = alpha * (rs1 * acc[mt][nt][3] + bp1 * b1);
            float* p0 = C + (size_t)r0 * ldc + col;
            float* p1 = C + (size_t)r1 * ldc + col;
            if (accumulate) {
                p0[0] += v00; p0[1] += v01;
                p1[0] += v10; p1[1] += v11;
            } else {
                *(float2*)p0 = make_float2(v00, v01);
                *(float2*)p1 = make_float2(v10, v11);
            }
        }
    }
}

// ---------------------------------------------------------------------------
// One block (128 thr) per dst node, one edge per iteration (R2 structure,
// 7 CTAs/SM occupancy), prefetch DEPTH 2 via 3-buffer cp.async ring.
// q and dst-key logits read per-lane from global (L1-resident dp row).
#define SORT_CAP 128
__global__ __launch_bounds__(128)
void node_attn_kernel(const int* __restrict__ off, const int* __restrict__ csr,
                      const float* __restrict__ dstproj,
                      const float* __restrict__ srcproj,
                      float* __restrict__ gsum) {
    __shared__ float svd[8][132];
    __shared__ float sks[3][8][132];
    __shared__ float svs[3][8][132];
    __shared__ int   elist[SORT_CAP];

    const int n = blockIdx.x;
    const int t = threadIdx.x;
    const int off0 = off[n];
    const int deg  = off[n + 1] - off0;
    if (deg == 0) return;

    const bool cached = (deg <= SORT_CAP);
    if (cached) {
        for (int i = t; i < deg; i += 128) elist[i] = csr[off0 + i];
    }
    const float* dp = dstproj + (size_t)n * (NS * 384);
    for (int i = t; i < 256; i += 128) {
        int s = i >> 5, c = i & 31;
        *(float4*)(&svd[s][c * 4]) = *(const float4*)(dp + s * 384 + 256 + c * 4);
    }
    __syncthreads();
    if (cached && t == 0) {   // sort for deterministic accumulation order
        for (int i = 1; i < deg; i++) {
            int v = elist[i], j = i - 1;
            while (j >= 0 && elist[j] > v) { elist[j + 1] = elist[j]; j--; }
            elist[j + 1] = v;
        }
    }
    __syncthreads();

    const int p  = t >> 2;     // (head, query) pair 0..31
    const int h  = p >> 3;
    const int qi = p & 7;
    const int g  = t & 3;
    const float scale = 0.17677669529663687f;   // 1/sqrt(32)

    // per-lane q slice (redundant across quad; L1 hits)
    float4 qr[8];
    #pragma unroll
    for (int u = 0; u < 8; u++)
        qr[u] = *(const float4*)(dp + qi * 384 + h * DH + u * 4);

    // precompute dst-key logits (keys g, g+4)
    float ldl[2];
    #pragma unroll
    for (int j = 0; j < 2; j++) {
        const float* kp = dp + (g + j * 4) * 384 + 128 + h * DH;
        float a = 0.f;
        #pragma unroll
        for (int u = 0; u < 8; u++) {
            float4 kr = *(const float4*)(kp + u * 4);
            a += qr[u].x * kr.x + qr[u].y * kr.y + qr[u].z * kr.z + qr[u].w * kr.w;
        }
        ldl[j] = a * scale;
    }

    float o[8];
    #pragma unroll
    for (int d = 0; d < 8; d++) o[d] = 0.f;

    auto stage = [&](int s) {
        int sn = cached ? elist[s] : csr[off0 + s];
        const float* sp = srcproj + (size_t)sn * (NS * 256);
        const int b = s % 3;
        #pragma unroll
        for (int r = 0; r < 2; r++) {
            int i = t + r * 128;
            int ss = i >> 5, c = i & 31;
            cp_async16(&sks[b][ss][c * 4], sp + ss * 256 + c * 4);
            cp_async16(&svs[b][ss][c * 4], sp + ss * 256 + 128 + c * 4);
        }
        cp_commit();
    };

    if (deg > 0) stage(0);
    if (deg > 1) stage(1);

    const int lbase = (t & 31) & ~3;
    for (int e = 0; e < deg; e++) {
        const int b = e % 3;
        if (e + 2 < deg) { stage(e + 2); cp_wait<2>(); }
        else if (e + 1 < deg) cp_wait<1>();
        else cp_wait<0>();
        __syncthreads();

        // src-key logits (keys 8+g, 12+g)
        float l[4];
        l[0] = ldl[0]; l[1] = ldl[1];
        #pragma unroll
        for (int j = 0; j < 2; j++) {
            int kk = g + j * 4;
            float a = 0.f;
            #pragma unroll
            for (int u = 0; u < 8; u++) {
                float4 kr = *(float4*)(&sks[b][kk][h * DH + u * 4]);
                a += qr[u].x * kr.x + qr[u].y * kr.y + qr[u].z * kr.z + qr[u].w * kr.w;
            }
            l[2 + j] = a * scale;
        }

        // softmax over 16 keys (4 local + quad shuffle)
        float m = fmaxf(fmaxf(l[0], l[1]), fmaxf(l[2], l[3]));
        m = fmaxf(m, __shfl_xor_sync(0xffffffffu, m, 1));
        m = fmaxf(m, __shfl_xor_sync(0xffffffffu, m, 2));
        float pr[4], es = 0.f;
        #pragma unroll
        for (int j = 0; j < 4; j++) { pr[j] = __expf(l[j] - m); es += pr[j]; }
        es += __shfl_xor_sync(0xffffffffu, es, 1);
        es += __shfl_xor_sync(0xffffffffu, es, 2);
        float inv = 1.f / es;
        float att[4];
        #pragma unroll
        for (int j = 0; j < 4; j++) att[j] = pr[j] * inv;

        // o += att @ [v_dst ; v_src]
        #pragma unroll
        for (int kk = 0; kk < 16; kk++) {
            float a = __shfl_sync(0xffffffffu, att[kk >> 2], lbase | (kk & 3));
            const float* vr = (kk < 8) ? &svd[kk][h * DH + g * 8]
                                       : &svs[b][kk - 8][h * DH + g * 8];
            #pragma unroll
            for (int d = 0; d < 8; d++) o[d] += a * vr[d];
        }
        __syncthreads();
    }

    float* outp = gsum + (size_t)n * (NS * DD) + qi * DD + h * DH + g * 8;
    *(float4*)outp       = make_float4(o[0], o[1], o[2], o[3]);
    *(float4*)(outp + 4) = make_float4(o[4], o[5], o[6], o[7]);
}

// ---------------------------------------------------------------------------
extern "C" void kernel_launch(void* const* d_in, const int* in_sizes, int n_in,
                              void* d_out, int out_size) {
    const float* x_a = (const float*)d_in[0];
    const float* x_b = (const float*)d_in[1];
    const int* ei[3] = {(const int*)d_in[2], (const int*)d_in[3], (const int*)d_in[4]};
    const int E  = in_sizes[2] / 2;
    const int Nn = in_sizes[0] / (NS * DD);
    const int M  = Nn * NS;

    float *dstproj, *srcproj, *sum, *cnt, *Wf, *bf;
    int *hist, *off, *cur, *csr;
    cudaGetSymbolAddress((void**)&dstproj, g_dstproj);
    cudaGetSymbolAddress((void**)&srcproj, g_srcproj);
    cudaGetSymbolAddress((void**)&sum, g_sum);
    cudaGetSymbolAddress((void**)&cnt, g_cnt);
    cudaGetSymbolAddress((void**)&Wf, g_Wf);
    cudaGetSymbolAddress((void**)&bf, g_bf);
    cudaGetSymbolAddress((void**)&hist, g_hist);
    cudaGetSymbolAddress((void**)&off, g_off);
    cudaGetSymbolAddress((void**)&cur, g_cur);
    cudaGetSymbolAddress((void**)&csr, g_csr);

    static int configured = -1;
    if (configured < 0) {
        cudaFuncSetAttribute(gemm_tf32,
                             cudaFuncAttributeMaxDynamicSharedMemorySize, GEMM_SMEM);
        configured = 1;
    }

    float* out = (float*)d_out;

    const float* xsrc[3] = {x_a, x_b, x_a};
    const float* xdst[3] = {x_b, x_a, x_a};
    float* outp[3]  = {out + (size_t)M * DD, out, out};
    float alpha[3]  = {1.f, 0.5f, 0.5f};
    int   accum[3]  = {0, 0, 1};

    for (int r = 0; r < 3; r++) {
        const float* Wb  = (const float*)d_in[5 + r * 6 + 0];
        const float* bb  = (const float*)d_in[5 + r * 6 + 1];
        const float* Win = (const float*)d_in[5 + r * 6 + 2];
        const float* bin = (const float*)d_in[5 + r * 6 + 3];
        const float* Wo  = (const float*)d_in[5 + r * 6 + 4];
        const float* bo  = (const float*)d_in[5 + r * 6 + 5];

        // ---- CSR build (by dst) ----
        zero2_int_kernel<<<(Nn + 255) / 256, 256>>>(hist, cur, Nn);
        hist_kernel<<<(E + 255) / 256, 256>>>(ei[r], E, hist);
        scan_kernel<<<1, 1024>>>(hist, off, Nn);
        scatter_kernel<<<(E + 255) / 256, 256>>>(ei[r], E, off, cur, csr);
        cnt_kernel<<<(Nn + 255) / 256, 256>>>(off, cnt, Nn);

        fold_kernel<<<128, 256>>>(Win, Wb, bb, bin, Wf, bf);

        // per-node projections (dst: q|k|v ; src: folded k|v)
        gemm_tf32<<<dim3(6, M / 128), 256, GEMM_SMEM>>>(xdst[r], Win, bin, dstproj, 384, nullptr, 1.f, 0);
        gemm_tf32<<<dim3(4, M / 128), 256, GEMM_SMEM>>>(xsrc[r], Wf, bf, srcproj, 256, nullptr, 1.f, 0);

        // grouped per-node attention + direct segment sum (no atomics)
        node_attn_kernel<<<Nn, 128>>>(off, csr, dstproj, srcproj, sum);

        // mean + Wo + bias (+combine across relations)
        gemm_tf32<<<dim3(2, M / 128), 256, GEMM_SMEM>>>(sum, Wo, bo, outp[r], DD, cnt, alpha[r], accum[r]);
    }
}

// round 6
// speedup vs baseline: 1.4164x; 1.0965x over previous
#include <cuda_runtime.h>
#include <cstdint>

#define NS 8          // tokens per node
#define DD 128        // model dim
#define NH 4          // heads
#define DH 32         // head dim

#define MAXN 20000
#define MAXM (MAXN * NS)          // 160000 rows
#define MAXE 100000

// -------- device scratch (allocation-free rule: __device__ globals) --------
// Per-relation sets so all three relations can run concurrently.
__device__ float g_dstproj[3][MAXM * 384];   // [q|k|v] per dst-node token
__device__ float g_srcproj[3][MAXM * 256];   // [k|v] per src-node token (Wb folded)
__device__ float g_sum[3][MAXM * DD];        // pre-Wo segment sum
__device__ float g_cnt[3][MAXN];
__device__ float g_Wf[3][256 * DD];          // folded [Wk@Wb ; Wv@Wb]
__device__ float g_bf[3][256];               // folded biases
__device__ int   g_hist[3][MAXN];
__device__ int   g_off[3][MAXN + 1];
__device__ int   g_cur[3][MAXN];
__device__ int   g_csr[3][MAXE];             // src node per edge, grouped by dst

// ---------------------------------------------------------------------------
__global__ void zero2_int_kernel(int* __restrict__ a, int* __restrict__ b, int n) {
    int i = blockIdx.x * blockDim.x + threadIdx.x;
    if (i < n) { a[i] = 0; b[i] = 0; }
}

__global__ void hist_kernel(const int* __restrict__ ei, int E, int* __restrict__ hist) {
    int i = blockIdx.x * blockDim.x + threadIdx.x;
    if (i < E) atomicAdd(hist + ei[E + i], 1);
}

__global__ __launch_bounds__(1024)
void scan_kernel(const int* __restrict__ hist, int* __restrict__ off, int N) {
    __shared__ int part[1025];
    const int t = threadIdx.x;
    const int chunk = (N + 1023) >> 10;
    const int lo = t * chunk;
    const int hi = min(lo + chunk, N);
    int s = 0;
    for (int i = lo; i < hi; i++) s += hist[i];
    part[t] = s;
    __syncthreads();
    if (t == 0) {
        int acc = 0;
        for (int i = 0; i < 1024; i++) { int v = part[i]; part[i] = acc; acc += v; }
        part[1024] = acc;
        off[N] = acc;
    }
    __syncthreads();
    int acc = part[t];
    for (int i = lo; i < hi; i++) { off[i] = acc; acc += hist[i]; }
}

__global__ void scatter_kernel(const int* __restrict__ ei, int E,
                               const int* __restrict__ off, int* __restrict__ cur,
                               int* __restrict__ csr) {
    int i = blockIdx.x * blockDim.x + threadIdx.x;
    if (i < E) {
        int dst = ei[E + i];
        int pos = atomicAdd(cur + dst, 1);
        csr[off[dst] + pos] = ei[i];
    }
}

__global__ void cnt_kernel(const int* __restrict__ off, float* __restrict__ cnt, int N) {
    int i = blockIdx.x * blockDim.x + threadIdx.x;
    if (i < N) cnt[i] = (float)(off[i + 1] - off[i]);
}

// Fold Wb into K/V projections: Wf[o,d] = sum_j Win[128+o, j] * Wb[j, d]
__global__ void fold_kernel(const float* __restrict__ Win, const float* __restrict__ Wb,
                            const float* __restrict__ bb, const float* __restrict__ bin,
                            float* __restrict__ Wf, float* __restrict__ bf) {
    int id = blockIdx.x * blockDim.x + threadIdx.x;
    int o = id >> 7, d = id & 127;
    const float* wrow = Win + (size_t)(128 + o) * DD;
    float acc = 0.f;
    #pragma unroll 8
    for (int j = 0; j < DD; j++) acc += wrow[j] * Wb[j * DD + d];
    Wf[o * DD + d] = acc;
    if (d == 0) {
        float b = 0.f;
        for (int j = 0; j < DD; j++) b += wrow[j] * bb[j];
        bf[o] = b + bin[128 + o];
    }
}

// ---------------------------------------------------------------------------
__device__ __forceinline__ uint32_t f2tf32(float x) {
    uint32_t r;
    asm("cvt.rna.tf32.f32 %0, %1;" : "=r"(r) : "f"(x));
    return r;
}

// C[M, Nout] = alpha * ( rowscale(A) @ B^T + bpresent*bias ), optionally +=.
// (exact R2 version: 128x64 tile, 8 warps 32x32, cvt at fill, static smem)
__global__ __launch_bounds__(256)
void gemm_tf32(const float* __restrict__ A, const float* __restrict__ B,
               const float* __restrict__ bias, float* __restrict__ C,
               int ldc, const float* __restrict__ cnt,
               float alpha, int accumulate) {
    __shared__ uint32_t As[128][36];
    __shared__ uint32_t Bs[64][36];

    const int t    = threadIdx.x;
    const int lane = t & 31;
    const int warp = t >> 5;
    const int wm   = warp >> 1;
    const int wn   = warp & 1;
    const int m0   = blockIdx.y * 128;
    const int n0   = blockIdx.x * 64;
    const int lg   = lane >> 2;
    const int lt   = lane & 3;

    float acc[2][4][4] = {};

    for (int k0 = 0; k0 < 128; k0 += 32) {
        #pragma unroll
        for (int r = 0; r < 4; r++) {
            int idx = t + r * 256;
            int row = idx >> 3, c4 = idx & 7;
            float4 v = *(const float4*)(A + (size_t)(m0 + row) * DD + k0 + c4 * 4);
            if (cnt) {
                float c = cnt[(m0 + row) >> 3];
                float rs = (c > 0.f) ? (1.f / c) : 0.f;
                v.x *= rs; v.y *= rs; v.z *= rs; v.w *= rs;
            }
            As[row][c4 * 4 + 0] = f2tf32(v.x);
            As[row][c4 * 4 + 1] = f2tf32(v.y);
            As[row][c4 * 4 + 2] = f2tf32(v.z);
            As[row][c4 * 4 + 3] = f2tf32(v.w);
        }
        #pragma unroll
        for (int r = 0; r < 2; r++) {
            int idx = t + r * 256;
            int row = idx >> 3, c4 = idx & 7;
            float4 v = *(const float4*)(B + (size_t)(n0 + row) * DD + k0 + c4 * 4);
            Bs[row][c4 * 4 + 0] = f2tf32(v.x);
            Bs[row][c4 * 4 + 1] = f2tf32(v.y);
            Bs[row][c4 * 4 + 2] = f2tf32(v.z);
            Bs[row][c4 * 4 + 3] = f2tf32(v.w);
        }
        __syncthreads();

        #pragma unroll
        for (int ks = 0; ks < 4; ks++) {
            const int kk = ks * 8;
            uint32_t af[2][4], bfr[4][2];
            #pragma unroll
            for (int mt = 0; mt < 2; mt++) {
                int rbase = wm * 32 + mt * 16;
                af[mt][0] = As[rbase + lg][kk + lt];
                af[mt][1] = As[rbase + 8 + lg][kk + lt];
                af[mt][2] = As[rbase + lg][kk + 4 + lt];
                af[mt][3] = As[rbase + 8 + lg][kk + 4 + lt];
            }
            #pragma unroll
            for (int nt = 0; nt < 4; nt++) {
                int nrow = wn * 32 + nt * 8 + lg;
                bfr[nt][0] = Bs[nrow][kk + lt];
                bfr[nt][1] = Bs[nrow][kk + 4 + lt];
            }
            #pragma unroll
            for (int mt = 0; mt < 2; mt++) {
                #pragma unroll
                for (int nt = 0; nt < 4; nt++) {
                    asm volatile(
                        "mma.sync.aligned.m16n8k8.row.col.f32.tf32.tf32.f32 "
                        "{%0,%1,%2,%3}, {%4,%5,%6,%7}, {%8,%9}, {%0,%1,%2,%3};"
                        : "+f"(acc[mt][nt][0]), "+f"(acc[mt][nt][1]),
                          "+f"(acc[mt][nt][2]), "+f"(acc[mt][nt][3])
                        : "r"(af[mt][0]), "r"(af[mt][1]), "r"(af[mt][2]), "r"(af[mt][3]),
                          "r"(bfr[nt][0]), "r"(bfr[nt][1]));
                }
            }
        }
        __syncthreads();
    }

    #pragma unroll
    for (int mt = 0; mt < 2; mt++) {
        int r0 = m0 + wm * 32 + mt * 16 + lg;
        int r1 = r0 + 8;
        float bp0 = 1.f, bp1 = 1.f;
        if (cnt) {
            bp0 = (cnt[r0 >> 3] > 0.f) ? 1.f : 0.f;
            bp1 = (cnt[r1 >> 3] > 0.f) ? 1.f : 0.f;
        }
        #pragma unroll
        for (int nt = 0; nt < 4; nt++) {
            int col = n0 + wn * 32 + nt * 8 + 2 * lt;
            float b0 = bias[col], b1 = bias[col + 1];
            float v00 = alpha * (acc[mt][nt][0] + bp0 * b0);
            float v01 = alpha * (acc[mt][nt][1] + bp0 * b1);
            float v10 = alpha * (acc[mt][nt][2] + bp1 * b0);
            float v11 = alpha * (acc[mt][nt][3] + bp1 * b1);
            float* p0 = C + (size_t)r0 * ldc + col;
            float* p1 = C + (size_t)r1 * ldc + col;
            if (accumulate) {
                p0[0] += v00; p0[1] += v01;
                p1[0] += v10; p1[1] += v11;
            } else {
                *(float2*)p0 = make_float2(v00, v01);
                *(float2*)p1 = make_float2(v10, v11);
            }
        }
    }
}

// ---------------------------------------------------------------------------
__device__ __forceinline__ void cp_async16(void* smem, const void* gmem) {
    uint32_t s = (uint32_t)__cvta_generic_to_shared(smem);
    asm volatile("cp.async.cg.shared.global [%0], [%1], 16;" :: "r"(s), "l"(gmem));
}
__device__ __forceinline__ void cp_commit() {
    asm volatile("cp.async.commit_group;");
}
template <int N> __device__ __forceinline__ void cp_wait() {
    asm volatile("cp.async.wait_group %0;" :: "n"(N));
}

// (exact R2 version) One block per dst node; dst q/k/v staged once; src k/v
// double-buffered via cp.async; no atomics; deterministic sorted order.
#define SORT_CAP 128
__global__ __launch_bounds__(128)
void node_attn_kernel(const int* __restrict__ off, const int* __restrict__ csr,
                      const float* __restrict__ dstproj,
                      const float* __restrict__ srcproj,
                      float* __restrict__ gsum) {
    __shared__ float sq[8][132];
    __shared__ float skd[8][132];
    __shared__ float svd[8][132];
    __shared__ float sks[2][8][132];
    __shared__ float svs[2][8][132];
    __shared__ int   elist[SORT_CAP];

    const int n = blockIdx.x;
    const int t = threadIdx.x;
    const int off0 = off[n];
    const int deg  = off[n + 1] - off0;
    if (deg == 0) return;

    const bool cached = (deg <= SORT_CAP);
    if (cached) {
        for (int i = t; i < deg; i += 128) elist[i] = csr[off0 + i];
        __syncthreads();
        if (t == 0) {
            for (int i = 1; i < deg; i++) {
                int v = elist[i], j = i - 1;
                while (j >= 0 && elist[j] > v) { elist[j + 1] = elist[j]; j--; }
                elist[j + 1] = v;
            }
        }
    }

    const float* dp = dstproj + (size_t)n * (NS * 384);
    for (int i = t; i < 256; i += 128) {
        int s = i >> 5, c = i & 31;
        *(float4*)(&sq[s][c * 4])  = *(const float4*)(dp + s * 384 + c * 4);
        *(float4*)(&skd[s][c * 4]) = *(const float4*)(dp + s * 384 + 128 + c * 4);
        *(float4*)(&svd[s][c * 4]) = *(const float4*)(dp + s * 384 + 256 + c * 4);
    }
    __syncthreads();

    const int p  = t >> 2;     // (head, query) pair 0..31
    const int h  = p >> 3;
    const int qi = p & 7;
    const int g  = t & 3;
    const float scale = 0.17677669529663687f;   // 1/sqrt(32)

    float4 qr[8];
    #pragma unroll
    for (int u = 0; u < 8; u++) qr[u] = *(float4*)(&sq[qi][h * DH + u * 4]);

    // precompute dst-key logits (keys g and g+4), scaled
    float ldl[2];
    #pragma unroll
    for (int j = 0; j < 2; j++) {
        int kk = g + j * 4;
        float acc = 0.f;
        #pragma unroll
        for (int u = 0; u < 8; u++) {
            float4 kr = *(float4*)(&skd[kk][h * DH + u * 4]);
            acc += qr[u].x * kr.x + qr[u].y * kr.y + qr[u].z * kr.z + qr[u].w * kr.w;
        }
        ldl[j] = acc * scale;
    }

    float o[8];
    #pragma unroll
    for (int d = 0; d < 8; d++) o[d] = 0.f;

    // prologue: stage edge 0 src k/v
    {
        int s0 = cached ? elist[0] : csr[off0];
        const float* sp = srcproj + (size_t)s0 * (NS * 256);
        #pragma unroll
        for (int r = 0; r < 2; r++) {
            int i = t + r * 128;
            int s = i >> 5, c = i & 31;
            cp_async16(&sks[0][s][c * 4], sp + s * 256 + c * 4);
            cp_async16(&svs[0][s][c * 4], sp + s * 256 + 128 + c * 4);
        }
        cp_commit();
    }

    const int lbase = (t & 31) & ~3;
    for (int e = 0; e < deg; e++) {
        const int b = e & 1;
        if (e + 1 < deg) {
            int sn = cached ? elist[e + 1] : csr[off0 + e + 1];
            const float* sp = srcproj + (size_t)sn * (NS * 256);
            #pragma unroll
            for (int r = 0; r < 2; r++) {
                int i = t + r * 128;
                int s = i >> 5, c = i & 31;
                cp_async16(&sks[b ^ 1][s][c * 4], sp + s * 256 + c * 4);
                cp_async16(&svs[b ^ 1][s][c * 4], sp + s * 256 + 128 + c * 4);
            }
            cp_commit();
            cp_wait<1>();
        } else {
            cp_wait<0>();
        }
        __syncthreads();

        // src-key logits (keys 8+g, 12+g)
        float l[4];
        l[0] = ldl[0]; l[1] = ldl[1];
        #pragma unroll
        for (int j = 0; j < 2; j++) {
            int kk = g + j * 4;
            float acc = 0.f;
            #pragma unroll
            for (int u = 0; u < 8; u++) {
                float4 kr = *(float4*)(&sks[b][kk][h * DH + u * 4]);
                acc += qr[u].x * kr.x + qr[u].y * kr.y + qr[u].z * kr.z + qr[u].w * kr.w;
            }
            l[2 + j] = acc * scale;
        }

        // softmax over 16 keys (4 local + quad shuffle)
        float m = fmaxf(fmaxf(l[0], l[1]), fmaxf(l[2], l[3]));
        m = fmaxf(m, __shfl_xor_sync(0xffffffffu, m, 1));
        m = fmaxf(m, __shfl_xor_sync(0xffffffffu, m, 2));
        float pr[4], es = 0.f;
        #pragma unroll
        for (int j = 0; j < 4; j++) { pr[j] = __expf(l[j] - m); es += pr[j]; }
        es += __shfl_xor_sync(0xffffffffu, es, 1);
        es += __shfl_xor_sync(0xffffffffu, es, 2);
        float inv = 1.f / es;
        float att[4];
        #pragma unroll
        for (int j = 0; j < 4; j++) att[j] = pr[j] * inv;

        // o += att @ [v_dst ; v_src]
        #pragma unroll
        for (int kk = 0; kk < 16; kk++) {
            float a = __shfl_sync(0xffffffffu, att[kk >> 2], lbase | (kk & 3));
            const float* vr = (kk < 8) ? &svd[kk][h * DH + g * 8]
                                       : &svs[b][kk - 8][h * DH + g * 8];
            #pragma unroll
            for (int d = 0; d < 8; d++) o[d] += a * vr[d];
        }
        __syncthreads();
    }

    float* outp = gsum + (size_t)n * (NS * DD) + qi * DD + h * DH + g * 8;
    *(float4*)outp       = make_float4(o[0], o[1], o[2], o[3]);
    *(float4*)(outp + 4) = make_float4(o[4], o[5], o[6], o[7]);
}

// ---------------------------------------------------------------------------
extern "C" void kernel_launch(void* const* d_in, const int* in_sizes, int n_in,
                              void* d_out, int out_size) {
    const float* x_a = (const float*)d_in[0];
    const float* x_b = (const float*)d_in[1];
    const int* ei[3] = {(const int*)d_in[2], (const int*)d_in[3], (const int*)d_in[4]};
    const int E  = in_sizes[2] / 2;
    const int Nn = in_sizes[0] / (NS * DD);
    const int M  = Nn * NS;

    float *dstprojB, *srcprojB, *sumB, *cntB, *WfB, *bfB;
    int *histB, *offB, *curB, *csrB;
    cudaGetSymbolAddress((void**)&dstprojB, g_dstproj);
    cudaGetSymbolAddress((void**)&srcprojB, g_srcproj);
    cudaGetSymbolAddress((void**)&sumB, g_sum);
    cudaGetSymbolAddress((void**)&cntB, g_cnt);
    cudaGetSymbolAddress((void**)&WfB, g_Wf);
    cudaGetSymbolAddress((void**)&bfB, g_bf);
    cudaGetSymbolAddress((void**)&histB, g_hist);
    cudaGetSymbolAddress((void**)&offB, g_off);
    cudaGetSymbolAddress((void**)&curB, g_cur);
    cudaGetSymbolAddress((void**)&csrB, g_csr);

    // one-time stream/event setup (outside capture on the correctness call;
    // reused as capturable fork-join dependencies afterwards)
    static cudaStream_t st[3] = {nullptr, nullptr, nullptr};
    static cudaEvent_t ev0 = nullptr, evDone[3] = {nullptr, nullptr, nullptr};
    if (!st[0]) {
        for (int i = 0; i < 3; i++) {
            cudaStreamCreateWithFlags(&st[i], cudaStreamNonBlocking);
            cudaEventCreateWithFlags(&evDone[i], cudaEventDisableTiming);
        }
        cudaEventCreateWithFlags(&ev0, cudaEventDisableTiming);
    }

    float* out = (float*)d_out;

    const float* xsrc[3] = {x_a, x_b, x_a};
    const float* xdst[3] = {x_b, x_a, x_a};
    float* outp[3]  = {out + (size_t)M * DD, out, out};
    float alphav[3] = {1.f, 0.5f, 0.5f};
    int   accumv[3] = {0, 0, 1};

    // fork: all three relation chains branch off the origin stream
    cudaEventRecord(ev0, 0);

    for (int r = 0; r < 3; r++) {
        cudaStream_t s = st[r];
        cudaStreamWaitEvent(s, ev0, 0);

        const float* Wb  = (const float*)d_in[5 + r * 6 + 0];
        const float* bb  = (const float*)d_in[5 + r * 6 + 1];
        const float* Win = (const float*)d_in[5 + r * 6 + 2];
        const float* bin = (const float*)d_in[5 + r * 6 + 3];
        const float* Wo  = (const float*)d_in[5 + r * 6 + 4];
        const float* bo  = (const float*)d_in[5 + r * 6 + 5];

        float* dstproj = dstprojB + (size_t)r * (MAXM * 384);
        float* srcproj = srcprojB + (size_t)r * (MAXM * 256);
        float* sum     = sumB     + (size_t)r * (MAXM * DD);
        float* cnt     = cntB     + (size_t)r * MAXN;
        float* Wf      = WfB      + (size_t)r * (256 * DD);
        float* bf      = bfB      + (size_t)r * 256;
        int*   hist    = histB    + (size_t)r * MAXN;
        int*   off     = offB     + (size_t)r * (MAXN + 1);
        int*   cur     = curB     + (size_t)r * MAXN;
        int*   csr     = csrB     + (size_t)r * MAXE;

        // ---- CSR build (by dst) ----
        zero2_int_kernel<<<(Nn + 255) / 256, 256, 0, s>>>(hist, cur, Nn);
        hist_kernel<<<(E + 255) / 256, 256, 0, s>>>(ei[r], E, hist);
        scan_kernel<<<1, 1024, 0, s>>>(hist, off, Nn);
        scatter_kernel<<<(E + 255) / 256, 256, 0, s>>>(ei[r], E, off, cur, csr);
        cnt_kernel<<<(Nn + 255) / 256, 256, 0, s>>>(off, cnt, Nn);

        fold_kernel<<<128, 256, 0, s>>>(Win, Wb, bb, bin, Wf, bf);

        // per-node projections (dst: q|k|v ; src: folded k|v)
        gemm_tf32<<<dim3(6, M / 128), 256, 0, s>>>(xdst[r], Win, bin, dstproj, 384, nullptr, 1.f, 0);
        gemm_tf32<<<dim3(4, M / 128), 256, 0, s>>>(xsrc[r], Wf, bf, srcproj, 256, nullptr, 1.f, 0);

        // grouped per-node attention + direct segment sum (no atomics)
        node_attn_kernel<<<Nn, 128, 0, s>>>(off, csr, dstproj, srcproj, sum);

        // r2 accumulates into out[0] after r1's plain write
        if (r == 2) cudaStreamWaitEvent(s, evDone[1], 0);

        // mean + Wo + bias (+combine across relations)
        gemm_tf32<<<dim3(2, M / 128), 256, 0, s>>>(sum, Wo, bo, outp[r], DD, cnt, alphav[r], accumv[r]);

        cudaEventRecord(evDone[r], s);
    }

    // join: origin stream waits for all three chains
    for (int r = 0; r < 3; r++) cudaStreamWaitEvent(0, evDone[r], 0);
}

// round 7
// speedup vs baseline: 1.4550x; 1.0273x over previous
#include <cuda_runtime.h>
#include <cstdint>

#define NS 8          // tokens per node
#define DD 128        // model dim
#define NH 4          // heads
#define DH 32         // head dim

#define MAXN 20000
#define MAXM (MAXN * NS)          // 160000 rows
#define MAXE 100000

// -------- device scratch (allocation-free rule: __device__ globals) --------
// Per-relation sets so all three relations can run concurrently.
__device__ float g_dstproj[3][MAXM * 384];   // [q|k|v] per dst-node token
__device__ float g_srcproj[3][MAXM * 256];   // [k|v] per src-node token (Wb folded)
__device__ float g_sum[3][MAXM * DD];        // pre-Wo segment sum
__device__ float g_cnt[3][MAXN];
__device__ float g_Wf[3][256 * DD];          // folded [Wk@Wb ; Wv@Wb]
__device__ float g_bf[3][256];               // folded biases
__device__ int   g_hist[3][MAXN];
__device__ int   g_off[3][MAXN + 1];
__device__ int   g_cur[3][MAXN];
__device__ int   g_csr[3][MAXE];             // src node per edge, grouped by dst

// ---------------------------------------------------------------------------
__global__ void zero2_int_kernel(int* __restrict__ a, int* __restrict__ b, int n) {
    int i = blockIdx.x * blockDim.x + threadIdx.x;
    if (i < n) { a[i] = 0; b[i] = 0; }
}

__global__ void hist_kernel(const int* __restrict__ ei, int E, int* __restrict__ hist) {
    int i = blockIdx.x * blockDim.x + threadIdx.x;
    if (i < E) atomicAdd(hist + ei[E + i], 1);
}

__global__ __launch_bounds__(1024)
void scan_kernel(const int* __restrict__ hist, int* __restrict__ off, int N) {
    __shared__ int part[1025];
    const int t = threadIdx.x;
    const int chunk = (N + 1023) >> 10;
    const int lo = t * chunk;
    const int hi = min(lo + chunk, N);
    int s = 0;
    for (int i = lo; i < hi; i++) s += hist[i];
    part[t] = s;
    __syncthreads();
    if (t == 0) {
        int acc = 0;
        for (int i = 0; i < 1024; i++) { int v = part[i]; part[i] = acc; acc += v; }
        part[1024] = acc;
        off[N] = acc;
    }
    __syncthreads();
    int acc = part[t];
    for (int i = lo; i < hi; i++) { off[i] = acc; acc += hist[i]; }
}

__global__ void scatter_kernel(const int* __restrict__ ei, int E,
                               const int* __restrict__ off, int* __restrict__ cur,
                               int* __restrict__ csr) {
    int i = blockIdx.x * blockDim.x + threadIdx.x;
    if (i < E) {
        int dst = ei[E + i];
        int pos = atomicAdd(cur + dst, 1);
        csr[off[dst] + pos] = ei[i];
    }
}

__global__ void cnt_kernel(const int* __restrict__ off, float* __restrict__ cnt, int N) {
    int i = blockIdx.x * blockDim.x + threadIdx.x;
    if (i < N) cnt[i] = (float)(off[i + 1] - off[i]);
}

// Fold Wb into K/V projections: Wf[o,d] = sum_j Win[128+o, j] * Wb[j, d]
__global__ void fold_kernel(const float* __restrict__ Win, const float* __restrict__ Wb,
                            const float* __restrict__ bb, const float* __restrict__ bin,
                            float* __restrict__ Wf, float* __restrict__ bf) {
    int id = blockIdx.x * blockDim.x + threadIdx.x;
    int o = id >> 7, d = id & 127;
    const float* wrow = Win + (size_t)(128 + o) * DD;
    float acc = 0.f;
    #pragma unroll 8
    for (int j = 0; j < DD; j++) acc += wrow[j] * Wb[j * DD + d];
    Wf[o * DD + d] = acc;
    if (d == 0) {
        float b = 0.f;
        for (int j = 0; j < DD; j++) b += wrow[j] * bb[j];
        bf[o] = b + bin[128 + o];
    }
}

// ---------------------------------------------------------------------------
__device__ __forceinline__ uint32_t f2tf32(float x) {
    uint32_t r;
    asm("cvt.rna.tf32.f32 %0, %1;" : "=r"(r) : "f"(x));
    return r;
}

// C[M, Nout] = alpha * ( rowscale(A) @ B^T + bpresent*bias ), optionally +=.
// 128x64 block tile, 8 warps 32x32. Register-prefetch pipeline: next k-tile's
// global loads issue before the MMA loop so LDG latency overlaps the MMAs.
// tf32 conversion stays at smem-fill time (NOT in the MMA inner loop).
__global__ __launch_bounds__(256)
void gemm_tf32(const float* __restrict__ A, const float* __restrict__ B,
               const float* __restrict__ bias, float* __restrict__ C,
               int ldc, const float* __restrict__ cnt,
               float alpha, int accumulate) {
    __shared__ uint32_t As[128][36];
    __shared__ uint32_t Bs[64][36];

    const int t    = threadIdx.x;
    const int lane = t & 31;
    const int warp = t >> 5;
    const int wm   = warp >> 1;
    const int wn   = warp & 1;
    const int m0   = blockIdx.y * 128;
    const int n0   = blockIdx.x * 64;
    const int lg   = lane >> 2;
    const int lt   = lane & 3;

    // per-thread staging coordinates (same for every tile)
    const int arow = t >> 3, ac4 = t & 7;          // + r*32 rows, 4 rows per 256 thr pass
    float acc[2][4][4] = {};
    float4 ra[4], rb[2];
    float rs_row[4];                                // rowscale for the 4 A rows staged

    #pragma unroll
    for (int r = 0; r < 4; r++) {
        rs_row[r] = 1.f;
        if (cnt) {
            float c = cnt[(m0 + arow + r * 32) >> 3];
            rs_row[r] = (c > 0.f) ? (1.f / c) : 0.f;
        }
    }

    auto gload = [&](int k0) {
        #pragma unroll
        for (int r = 0; r < 4; r++)
            ra[r] = *(const float4*)(A + (size_t)(m0 + arow + r * 32) * DD + k0 + ac4 * 4);
        #pragma unroll
        for (int r = 0; r < 2; r++)
            rb[r] = *(const float4*)(B + (size_t)(n0 + arow + r * 32) * DD + k0 + ac4 * 4);
    };
    auto sstore = [&]() {
        #pragma unroll
        for (int r = 0; r < 4; r++) {
            float4 v = ra[r];
            float rs = rs_row[r];
            int row = arow + r * 32;
            As[row][ac4 * 4 + 0] = f2tf32(v.x * rs);
            As[row][ac4 * 4 + 1] = f2tf32(v.y * rs);
            As[row][ac4 * 4 + 2] = f2tf32(v.z * rs);
            As[row][ac4 * 4 + 3] = f2tf32(v.w * rs);
        }
        #pragma unroll
        for (int r = 0; r < 2; r++) {
            float4 v = rb[r];
            int row = arow + r * 32;
            Bs[row][ac4 * 4 + 0] = f2tf32(v.x);
            Bs[row][ac4 * 4 + 1] = f2tf32(v.y);
            Bs[row][ac4 * 4 + 2] = f2tf32(v.z);
            Bs[row][ac4 * 4 + 3] = f2tf32(v.w);
        }
    };

    gload(0);

    #pragma unroll
    for (int kc = 0; kc < 4; kc++) {
        sstore();
        __syncthreads();
        if (kc < 3) gload((kc + 1) * 32);   // LDG latency hides under MMAs below

        #pragma unroll
        for (int ks = 0; ks < 4; ks++) {
            const int kk = ks * 8;
            uint32_t af[2][4], bfr[4][2];
            #pragma unroll
            for (int mt = 0; mt < 2; mt++) {
                int rbase = wm * 32 + mt * 16;
                af[mt][0] = As[rbase + lg][kk + lt];
                af[mt][1] = As[rbase + 8 + lg][kk + lt];
                af[mt][2] = As[rbase + lg][kk + 4 + lt];
                af[mt][3] = As[rbase + 8 + lg][kk + 4 + lt];
            }
            #pragma unroll
            for (int nt = 0; nt < 4; nt++) {
                int nrow = wn * 32 + nt * 8 + lg;
                bfr[nt][0] = Bs[nrow][kk + lt];
                bfr[nt][1] = Bs[nrow][kk + 4 + lt];
            }
            #pragma unroll
            for (int mt = 0; mt < 2; mt++) {
                #pragma unroll
                for (int nt = 0; nt < 4; nt++) {
                    asm volatile(
                        "mma.sync.aligned.m16n8k8.row.col.f32.tf32.tf32.f32 "
                        "{%0,%1,%2,%3}, {%4,%5,%6,%7}, {%8,%9}, {%0,%1,%2,%3};"
                        : "+f"(acc[mt][nt][0]), "+f"(acc[mt][nt][1]),
                          "+f"(acc[mt][nt][2]), "+f"(acc[mt][nt][3])
                        : "r"(af[mt][0]), "r"(af[mt][1]), "r"(af[mt][2]), "r"(af[mt][3]),
                          "r"(bfr[nt][0]), "r"(bfr[nt][1]));
                }
            }
        }
        __syncthreads();
    }

    #pragma unroll
    for (int mt = 0; mt < 2; mt++) {
        int r0 = m0 + wm * 32 + mt * 16 + lg;
        int r1 = r0 + 8;
        float bp0 = 1.f, bp1 = 1.f;
        if (cnt) {
            bp0 = (cnt[r0 >> 3] > 0.f) ? 1.f : 0.f;
            bp1 = (cnt[r1 >> 3] > 0.f) ? 1.f : 0.f;
        }
        #pragma unroll
        for (int nt = 0; nt < 4; nt++) {
            int col = n0 + wn * 32 + nt * 8 + 2 * lt;
            float b0 = bias[col], b1 = bias[col + 1];
            float v00 = alpha * (acc[mt][nt][0] + bp0 * b0);
            float v01 = alpha * (acc[mt][nt][1] + bp0 * b1);
            float v10 = alpha * (acc[mt][nt][2] + bp1 * b0);
            float v11 = alpha * (acc[mt][nt][3] + bp1 * b1);
            float* p0 = C + (size_t)r0 * ldc + col;
            float* p1 = C + (size_t)r1 * ldc + col;
            if (accumulate) {
                p0[0] += v00; p0[1] += v01;
                p1[0] += v10; p1[1] += v11;
            } else {
                *(float2*)p0 = make_float2(v00, v01);
                *(float2*)p1 = make_float2(v10, v11);
            }
        }
    }
}

// ---------------------------------------------------------------------------
__device__ __forceinline__ void cp_async16(void* smem, const void* gmem) {
    uint32_t s = (uint32_t)__cvta_generic_to_shared(smem);
    asm volatile("cp.async.cg.shared.global [%0], [%1], 16;" :: "r"(s), "l"(gmem));
}
__device__ __forceinline__ void cp_commit() {
    asm volatile("cp.async.commit_group;");
}
template <int N> __device__ __forceinline__ void cp_wait() {
    asm volatile("cp.async.wait_group %0;" :: "n"(N));
}

// (exact R2 version) One block per dst node; dst q/k/v staged once; src k/v
// double-buffered via cp.async; no atomics; deterministic sorted order.
#define SORT_CAP 128
__global__ __launch_bounds__(128)
void node_attn_kernel(const int* __restrict__ off, const int* __restrict__ csr,
                      const float* __restrict__ dstproj,
                      const float* __restrict__ srcproj,
                      float* __restrict__ gsum) {
    __shared__ float sq[8][132];
    __shared__ float skd[8][132];
    __shared__ float svd[8][132];
    __shared__ float sks[2][8][132];
    __shared__ float svs[2][8][132];
    __shared__ int   elist[SORT_CAP];

    const int n = blockIdx.x;
    const int t = threadIdx.x;
    const int off0 = off[n];
    const int deg  = off[n + 1] - off0;
    if (deg == 0) return;

    const bool cached = (deg <= SORT_CAP);
    if (cached) {
        for (int i = t; i < deg; i += 128) elist[i] = csr[off0 + i];
        __syncthreads();
        if (t == 0) {
            for (int i = 1; i < deg; i++) {
                int v = elist[i], j = i - 1;
                while (j >= 0 && elist[j] > v) { elist[j + 1] = elist[j]; j--; }
                elist[j + 1] = v;
            }
        }
    }

    const float* dp = dstproj + (size_t)n * (NS * 384);
    for (int i = t; i < 256; i += 128) {
        int s = i >> 5, c = i & 31;
        *(float4*)(&sq[s][c * 4])  = *(const float4*)(dp + s * 384 + c * 4);
        *(float4*)(&skd[s][c * 4]) = *(const float4*)(dp + s * 384 + 128 + c * 4);
        *(float4*)(&svd[s][c * 4]) = *(const float4*)(dp + s * 384 + 256 + c * 4);
    }
    __syncthreads();

    const int p  = t >> 2;     // (head, query) pair 0..31
    const int h  = p >> 3;
    const int qi = p & 7;
    const int g  = t & 3;
    const float scale = 0.17677669529663687f;   // 1/sqrt(32)

    float4 qr[8];
    #pragma unroll
    for (int u = 0; u < 8; u++) qr[u] = *(float4*)(&sq[qi][h * DH + u * 4]);

    // precompute dst-key logits (keys g and g+4), scaled
    float ldl[2];
    #pragma unroll
    for (int j = 0; j < 2; j++) {
        int kk = g + j * 4;
        float acc = 0.f;
        #pragma unroll
        for (int u = 0; u < 8; u++) {
            float4 kr = *(float4*)(&skd[kk][h * DH + u * 4]);
            acc += qr[u].x * kr.x + qr[u].y * kr.y + qr[u].z * kr.z + qr[u].w * kr.w;
        }
        ldl[j] = acc * scale;
    }

    float o[8];
    #pragma unroll
    for (int d = 0; d < 8; d++) o[d] = 0.f;

    // prologue: stage edge 0 src k/v
    {
        int s0 = cached ? elist[0] : csr[off0];
        const float* sp = srcproj + (size_t)s0 * (NS * 256);
        #pragma unroll
        for (int r = 0; r < 2; r++) {
            int i = t + r * 128;
            int s = i >> 5, c = i & 31;
            cp_async16(&sks[0][s][c * 4], sp + s * 256 + c * 4);
            cp_async16(&svs[0][s][c * 4], sp + s * 256 + 128 + c * 4);
        }
        cp_commit();
    }

    const int lbase = (t & 31) & ~3;
    for (int e = 0; e < deg; e++) {
        const int b = e & 1;
        if (e + 1 < deg) {
            int sn = cached ? elist[e + 1] : csr[off0 + e + 1];
            const float* sp = srcproj + (size_t)sn * (NS * 256);
            #pragma unroll
            for (int r = 0; r < 2; r++) {
                int i = t + r * 128;
                int s = i >> 5, c = i & 31;
                cp_async16(&sks[b ^ 1][s][c * 4], sp + s * 256 + c * 4);
                cp_async16(&svs[b ^ 1][s][c * 4], sp + s * 256 + 128 + c * 4);
            }
            cp_commit();
            cp_wait<1>();
        } else {
            cp_wait<0>();
        }
        __syncthreads();

        // src-key logits (keys 8+g, 12+g)
        float l[4];
        l[0] = ldl[0]; l[1] = ldl[1];
        #pragma unroll
        for (int j = 0; j < 2; j++) {
            int kk = g + j * 4;
            float acc = 0.f;
            #pragma unroll
            for (int u = 0; u < 8; u++) {
                float4 kr = *(float4*)(&sks[b][kk][h * DH + u * 4]);
                acc += qr[u].x * kr.x + qr[u].y * kr.y + qr[u].z * kr.z + qr[u].w * kr.w;
            }
            l[2 + j] = acc * scale;
        }

        // softmax over 16 keys (4 local + quad shuffle)
        float m = fmaxf(fmaxf(l[0], l[1]), fmaxf(l[2], l[3]));
        m = fmaxf(m, __shfl_xor_sync(0xffffffffu, m, 1));
        m = fmaxf(m, __shfl_xor_sync(0xffffffffu, m, 2));
        float pr[4], es = 0.f;
        #pragma unroll
        for (int j = 0; j < 4; j++) { pr[j] = __expf(l[j] - m); es += pr[j]; }
        es += __shfl_xor_sync(0xffffffffu, es, 1);
        es += __shfl_xor_sync(0xffffffffu, es, 2);
        float inv = 1.f / es;
        float att[4];
        #pragma unroll
        for (int j = 0; j < 4; j++) att[j] = pr[j] * inv;

        // o += att @ [v_dst ; v_src]
        #pragma unroll
        for (int kk = 0; kk < 16; kk++) {
            float a = __shfl_sync(0xffffffffu, att[kk >> 2], lbase | (kk & 3));
            const float* vr = (kk < 8) ? &svd[kk][h * DH + g * 8]
                                       : &svs[b][kk - 8][h * DH + g * 8];
            #pragma unroll
            for (int d = 0; d < 8; d++) o[d] += a * vr[d];
        }
        __syncthreads();
    }

    float* outp = gsum + (size_t)n * (NS * DD) + qi * DD + h * DH + g * 8;
    *(float4*)outp       = make_float4(o[0], o[1], o[2], o[3]);
    *(float4*)(outp + 4) = make_float4(o[4], o[5], o[6], o[7]);
}

// ---------------------------------------------------------------------------
extern "C" void kernel_launch(void* const* d_in, const int* in_sizes, int n_in,
                              void* d_out, int out_size) {
    const float* x_a = (const float*)d_in[0];
    const float* x_b = (const float*)d_in[1];
    const int* ei[3] = {(const int*)d_in[2], (const int*)d_in[3], (const int*)d_in[4]};
    const int E  = in_sizes[2] / 2;
    const int Nn = in_sizes[0] / (NS * DD);
    const int M  = Nn * NS;

    float *dstprojB, *srcprojB, *sumB, *cntB, *WfB, *bfB;
    int *histB, *offB, *curB, *csrB;
    cudaGetSymbolAddress((void**)&dstprojB, g_dstproj);
    cudaGetSymbolAddress((void**)&srcprojB, g_srcproj);
    cudaGetSymbolAddress((void**)&sumB, g_sum);
    cudaGetSymbolAddress((void**)&cntB, g_cnt);
    cudaGetSymbolAddress((void**)&WfB, g_Wf);
    cudaGetSymbolAddress((void**)&bfB, g_bf);
    cudaGetSymbolAddress((void**)&histB, g_hist);
    cudaGetSymbolAddress((void**)&offB, g_off);
    cudaGetSymbolAddress((void**)&curB, g_cur);
    cudaGetSymbolAddress((void**)&csrB, g_csr);

    // one-time stream/event setup (outside capture on the correctness call;
    // reused as capturable fork-join dependencies afterwards)
    static cudaStream_t st[3] = {nullptr, nullptr, nullptr};
    static cudaEvent_t ev0 = nullptr, evDone[3] = {nullptr, nullptr, nullptr};
    if (!st[0]) {
        for (int i = 0; i < 3; i++) {
            cudaStreamCreateWithFlags(&st[i], cudaStreamNonBlocking);
            cudaEventCreateWithFlags(&evDone[i], cudaEventDisableTiming);
        }
        cudaEventCreateWithFlags(&ev0, cudaEventDisableTiming);
    }

    float* out = (float*)d_out;

    const float* xsrc[3] = {x_a, x_b, x_a};
    const float* xdst[3] = {x_b, x_a, x_a};
    float* outp[3]  = {out + (size_t)M * DD, out, out};
    float alphav[3] = {1.f, 0.5f, 0.5f};
    int   accumv[3] = {0, 0, 1};

    // fork: all three relation chains branch off the origin stream
    cudaEventRecord(ev0, 0);

    for (int r = 0; r < 3; r++) {
        cudaStream_t s = st[r];
        cudaStreamWaitEvent(s, ev0, 0);

        const float* Wb  = (const float*)d_in[5 + r * 6 + 0];
        const float* bb  = (const float*)d_in[5 + r * 6 + 1];
        const float* Win = (const float*)d_in[5 + r * 6 + 2];
        const float* bin = (const float*)d_in[5 + r * 6 + 3];
        const float* Wo  = (const float*)d_in[5 + r * 6 + 4];
        const float* bo  = (const float*)d_in[5 + r * 6 + 5];

        float* dstproj = dstprojB + (size_t)r * (MAXM * 384);
        float* srcproj = srcprojB + (size_t)r * (MAXM * 256);
        float* sum     = sumB     + (size_t)r * (MAXM * DD);
        float* cnt     = cntB     + (size_t)r * MAXN;
        float* Wf      = WfB      + (size_t)r * (256 * DD);
        float* bf      = bfB      + (size_t)r * 256;
        int*   hist    = histB    + (size_t)r * MAXN;
        int*   off     = offB     + (size_t)r * (MAXN + 1);
        int*   cur     = curB     + (size_t)r * MAXN;
        int*   csr     = csrB     + (size_t)r * MAXE;

        // ---- CSR build (by dst) ----
        zero2_int_kernel<<<(Nn + 255) / 256, 256, 0, s>>>(hist, cur, Nn);
        hist_kernel<<<(E + 255) / 256, 256, 0, s>>>(ei[r], E, hist);
        scan_kernel<<<1, 1024, 0, s>>>(hist, off, Nn);
        scatter_kernel<<<(E + 255) / 256, 256, 0, s>>>(ei[r], E, off, cur, csr);
        cnt_kernel<<<(Nn + 255) / 256, 256, 0, s>>>(off, cnt, Nn);

        fold_kernel<<<128, 256, 0, s>>>(Win, Wb, bb, bin, Wf, bf);

        // per-node projections (dst: q|k|v ; src: folded k|v)
        gemm_tf32<<<dim3(6, M / 128), 256, 0, s>>>(xdst[r], Win, bin, dstproj, 384, nullptr, 1.f, 0);
        gemm_tf32<<<dim3(4, M / 128), 256, 0, s>>>(xsrc[r], Wf, bf, srcproj, 256, nullptr, 1.f, 0);

        // grouped per-node attention + direct segment sum (no atomics)
        node_attn_kernel<<<Nn, 128, 0, s>>>(off, csr, dstproj, srcproj, sum);

        // r2 accumulates into out[0] after r1's plain write
        if (r == 2) cudaStreamWaitEvent(s, evDone[1], 0);

        // mean + Wo + bias (+combine across relations)
        gemm_tf32<<<dim3(2, M / 128), 256, 0, s>>>(sum, Wo, bo, outp[r], DD, cnt, alphav[r], accumv[r]);

        cudaEventRecord(evDone[r], s);
    }

    // join: origin stream waits for all three chains
    for (int r = 0; r < 3; r++) cudaStreamWaitEvent(0, evDone[r], 0);
}